// round 2
// baseline (speedup 1.0000x reference)
#include <cuda_runtime.h>
#include <math.h>

#define BATCH 2
#define CH    512
#define NS    4096   // d*h*w = 16*16*16
#define NGRP  32

#define TBM 64
#define TBN 64
#define TBK 16

// -------- scratch (static device memory; no allocations allowed) ----------
__device__ float g_h[BATCH * CH * NS];
__device__ float g_q[BATCH * CH * NS];
__device__ float g_k[BATCH * CH * NS];
__device__ float g_v[BATCH * CH * NS];
__device__ float g_o[BATCH * CH * NS];
__device__ float g_attn[(size_t)BATCH * NS * NS];   // 128 MB

// ---------------------------- GroupNorm -----------------------------------
// one block per (batch, group); group = 16 channels x 4096 spatial = 65536 floats
__global__ void __launch_bounds__(256) gn_kernel(
    const float* __restrict__ x, const float* __restrict__ gamma,
    const float* __restrict__ beta, float* __restrict__ hout)
{
    int blk = blockIdx.x;
    int b = blk >> 5, grp = blk & 31;
    size_t base = ((size_t)(b * CH + grp * 16)) * NS;
    const float4* x4 = (const float4*)(x + base);
    float4* h4 = (float4*)(hout + base);
    const int n4 = 16 * NS / 4;   // 16384 float4s

    float s = 0.f, ss = 0.f;
    for (int i = threadIdx.x; i < n4; i += 256) {
        float4 v = x4[i];
        s  += v.x + v.y + v.z + v.w;
        ss += v.x * v.x + v.y * v.y + v.z * v.z + v.w * v.w;
    }
    __shared__ float rs[256], rss[256];
    rs[threadIdx.x] = s; rss[threadIdx.x] = ss;
    __syncthreads();
    for (int st = 128; st > 0; st >>= 1) {
        if (threadIdx.x < st) {
            rs[threadIdx.x]  += rs[threadIdx.x + st];
            rss[threadIdx.x] += rss[threadIdx.x + st];
        }
        __syncthreads();
    }
    const float inv_n = 1.f / (16.f * NS);
    float mean = rs[0] * inv_n;
    float var  = rss[0] * inv_n - mean * mean;
    float inv  = rsqrtf(var + 1e-6f);

    for (int i = threadIdx.x; i < n4; i += 256) {
        int c = grp * 16 + (i >> 10);          // 1024 float4s per channel
        float ga = gamma[c] * inv;
        float be = beta[c] - mean * ga;
        float4 v = x4[i];
        float4 o;
        o.x = v.x * ga + be; o.y = v.y * ga + be;
        o.z = v.z * ga + be; o.w = v.w * ga + be;
        h4[i] = o;
    }
}

// ---------------------------- Softmax (rows of 4096) -----------------------
__global__ void __launch_bounds__(256) softmax_kernel(float* __restrict__ attn)
{
    float4* p = (float4*)(attn + (size_t)blockIdx.x * NS);
    __shared__ float red[256];
    int t = threadIdx.x;

    float m = -1e30f;
    for (int i = t; i < NS / 4; i += 256) {
        float4 v = p[i];
        m = fmaxf(m, fmaxf(fmaxf(v.x, v.y), fmaxf(v.z, v.w)));
    }
    red[t] = m; __syncthreads();
    for (int st = 128; st > 0; st >>= 1) {
        if (t < st) red[t] = fmaxf(red[t], red[t + st]);
        __syncthreads();
    }
    m = red[0];
    __syncthreads();

    float s = 0.f;
    for (int i = t; i < NS / 4; i += 256) {
        float4 v = p[i];
        v.x = __expf(v.x - m); v.y = __expf(v.y - m);
        v.z = __expf(v.z - m); v.w = __expf(v.w - m);
        p[i] = v;
        s += v.x + v.y + v.z + v.w;
    }
    red[t] = s; __syncthreads();
    for (int st = 128; st > 0; st >>= 1) {
        if (t < st) red[t] += red[t + st];
        __syncthreads();
    }
    float inv = 1.f / red[0];
    for (int i = t; i < NS / 4; i += 256) {
        float4 v = p[i];
        v.x *= inv; v.y *= inv; v.z *= inv; v.w *= inv;
        p[i] = v;
    }
}

// ------------------- GEMM NN: C[m,n] = A[m,k]*B[k,n] (+bias[m]) (+res) -----
// A: weights [M,K] row-major, shared across batch. B,C,res batched by stride.
__global__ void __launch_bounds__(256) gemm_nn(
    const float* __restrict__ A, const float* __restrict__ B,
    float* __restrict__ Cmat, const float* __restrict__ bias,
    const float* __restrict__ res,
    int M, int Nn, int K, long long sB, long long sC, long long sR)
{
    const float* Bp = B + (long long)blockIdx.z * sB;
    float* Cp = Cmat + (long long)blockIdx.z * sC;
    const float* Rp = res ? res + (long long)blockIdx.z * sR : nullptr;

    __shared__ float As[TBM][TBK + 1];
    __shared__ float Bs[TBK][TBN];
    const int tid = threadIdx.x;
    const int tx = tid & 15, ty = tid >> 4;
    const int m0 = blockIdx.y * TBM, n0 = blockIdx.x * TBN;
    const int ar = tid >> 2, ac = (tid & 3) * 4;
    const int br = tid >> 4, bc = (tid & 15) * 4;

    float acc[4][4] = {};
    for (int k0 = 0; k0 < K; k0 += TBK) {
        float4 av = *(const float4*)(A + (size_t)(m0 + ar) * K + k0 + ac);
        As[ar][ac] = av.x; As[ar][ac + 1] = av.y;
        As[ar][ac + 2] = av.z; As[ar][ac + 3] = av.w;
        *(float4*)&Bs[br][bc] = *(const float4*)(Bp + (size_t)(k0 + br) * Nn + n0 + bc);
        __syncthreads();
#pragma unroll
        for (int kk = 0; kk < TBK; kk++) {
            float a[4], bb[4];
#pragma unroll
            for (int i = 0; i < 4; i++) a[i] = As[ty * 4 + i][kk];
#pragma unroll
            for (int j = 0; j < 4; j++) bb[j] = Bs[kk][tx * 4 + j];
#pragma unroll
            for (int i = 0; i < 4; i++)
#pragma unroll
                for (int j = 0; j < 4; j++)
                    acc[i][j] = fmaf(a[i], bb[j], acc[i][j]);
        }
        __syncthreads();
    }
#pragma unroll
    for (int i = 0; i < 4; i++) {
        int m = m0 + ty * 4 + i;
        float bi = bias ? bias[m] : 0.f;
#pragma unroll
        for (int j = 0; j < 4; j++) {
            int n = n0 + tx * 4 + j;
            float v = acc[i][j] + bi;
            if (Rp) v += Rp[(size_t)m * Nn + n];
            Cp[(size_t)m * Nn + n] = v;
        }
    }
}

// ------------- GEMM TN: C[m,n] = scale * sum_k A[k,m]*B[k,n] ---------------
// A: [K, M] k-major (lda = M), B: [K, N] (ldb = N). Used for scores QtK.
__global__ void __launch_bounds__(256) gemm_tn(
    const float* __restrict__ A, const float* __restrict__ B,
    float* __restrict__ Cmat, float scale,
    int M, int Nn, int K, long long sA, long long sB, long long sC)
{
    const float* Ap = A + (long long)blockIdx.z * sA;
    const float* Bp = B + (long long)blockIdx.z * sB;
    float* Cp = Cmat + (long long)blockIdx.z * sC;

    __shared__ float As[TBK][TBM];
    __shared__ float Bs[TBK][TBN];
    const int tid = threadIdx.x;
    const int tx = tid & 15, ty = tid >> 4;
    const int m0 = blockIdx.y * TBM, n0 = blockIdx.x * TBN;
    const int r = tid >> 4, c = (tid & 15) * 4;

    float acc[4][4] = {};
    for (int k0 = 0; k0 < K; k0 += TBK) {
        *(float4*)&As[r][c] = *(const float4*)(Ap + (size_t)(k0 + r) * M  + m0 + c);
        *(float4*)&Bs[r][c] = *(const float4*)(Bp + (size_t)(k0 + r) * Nn + n0 + c);
        __syncthreads();
#pragma unroll
        for (int kk = 0; kk < TBK; kk++) {
            float a[4], bb[4];
#pragma unroll
            for (int i = 0; i < 4; i++) a[i] = As[kk][ty * 4 + i];
#pragma unroll
            for (int j = 0; j < 4; j++) bb[j] = Bs[kk][tx * 4 + j];
#pragma unroll
            for (int i = 0; i < 4; i++)
#pragma unroll
                for (int j = 0; j < 4; j++)
                    acc[i][j] = fmaf(a[i], bb[j], acc[i][j]);
        }
        __syncthreads();
    }
#pragma unroll
    for (int i = 0; i < 4; i++) {
        int m = m0 + ty * 4 + i;
#pragma unroll
        for (int j = 0; j < 4; j++)
            Cp[(size_t)m * Nn + n0 + tx * 4 + j] = acc[i][j] * scale;
    }
}

// ------------- GEMM NT: C[m,n] = sum_k A[m,k]*B[n,k] -----------------------
// A: [M, K] row-major (lda = K), B: [N, K] row-major (ldb = K). Used for P·Vt.
__global__ void __launch_bounds__(256) gemm_nt(
    const float* __restrict__ A, const float* __restrict__ B,
    float* __restrict__ Cmat,
    int M, int Nn, int K, long long sA, long long sB, long long sC)
{
    const float* Ap = A + (long long)blockIdx.z * sA;
    const float* Bp = B + (long long)blockIdx.z * sB;
    float* Cp = Cmat + (long long)blockIdx.z * sC;

    __shared__ float As[TBM][TBK + 1];
    __shared__ float Bs[TBK][TBN + 1];
    const int tid = threadIdx.x;
    const int tx = tid & 15, ty = tid >> 4;
    const int m0 = blockIdx.y * TBM, n0 = blockIdx.x * TBN;
    const int ar = tid >> 2, ac = (tid & 3) * 4;

    float acc[4][4] = {};
    for (int k0 = 0; k0 < K; k0 += TBK) {
        float4 av = *(const float4*)(Ap + (size_t)(m0 + ar) * K + k0 + ac);
        As[ar][ac] = av.x; As[ar][ac + 1] = av.y;
        As[ar][ac + 2] = av.z; As[ar][ac + 3] = av.w;
        float4 bv = *(const float4*)(Bp + (size_t)(n0 + ar) * K + k0 + ac);
        Bs[ac][ar] = bv.x; Bs[ac + 1][ar] = bv.y;
        Bs[ac + 2][ar] = bv.z; Bs[ac + 3][ar] = bv.w;
        __syncthreads();
#pragma unroll
        for (int kk = 0; kk < TBK; kk++) {
            float a[4], bb[4];
#pragma unroll
            for (int i = 0; i < 4; i++) a[i] = As[ty * 4 + i][kk];
#pragma unroll
            for (int j = 0; j < 4; j++) bb[j] = Bs[kk][tx * 4 + j];
#pragma unroll
            for (int i = 0; i < 4; i++)
#pragma unroll
                for (int j = 0; j < 4; j++)
                    acc[i][j] = fmaf(a[i], bb[j], acc[i][j]);
        }
        __syncthreads();
    }
#pragma unroll
    for (int i = 0; i < 4; i++) {
        int m = m0 + ty * 4 + i;
#pragma unroll
        for (int j = 0; j < 4; j++)
            Cp[(size_t)m * Nn + n0 + tx * 4 + j] = acc[i][j];
    }
}

// --------------------------------- launch ----------------------------------
extern "C" void kernel_launch(void* const* d_in, const int* in_sizes, int n_in,
                              void* d_out, int out_size)
{
    const float* x     = (const float*)d_in[0];
    const float* gamma = (const float*)d_in[1];
    const float* beta  = (const float*)d_in[2];
    const float* wq = (const float*)d_in[3];
    const float* bq = (const float*)d_in[4];
    const float* wk = (const float*)d_in[5];
    const float* bk = (const float*)d_in[6];
    const float* wv = (const float*)d_in[7];
    const float* bv = (const float*)d_in[8];
    const float* wo = (const float*)d_in[9];
    const float* bo = (const float*)d_in[10];
    float* out = (float*)d_out;

    float *hP, *qP, *kP, *vP, *oP, *aP;
    cudaGetSymbolAddress((void**)&hP, g_h);
    cudaGetSymbolAddress((void**)&qP, g_q);
    cudaGetSymbolAddress((void**)&kP, g_k);
    cudaGetSymbolAddress((void**)&vP, g_v);
    cudaGetSymbolAddress((void**)&oP, g_o);
    cudaGetSymbolAddress((void**)&aP, g_attn);

    const long long SB = (long long)CH * NS;   // per-batch stride for [C,N] tensors
    const long long SA = (long long)NS * NS;   // per-batch stride for attn

    // 1) GroupNorm
    gn_kernel<<<BATCH * NGRP, 256>>>(x, gamma, beta, hP);

    // 2) Q, K, V projections: [512x512] @ [512x4096]
    dim3 gq(NS / TBN, CH / TBM, BATCH);
    gemm_nn<<<gq, 256>>>(wq, hP, qP, bq, nullptr, CH, NS, CH, SB, SB, 0);
    gemm_nn<<<gq, 256>>>(wk, hP, kP, bk, nullptr, CH, NS, CH, SB, SB, 0);
    gemm_nn<<<gq, 256>>>(wv, hP, vP, bv, nullptr, CH, NS, CH, SB, SB, 0);

    // 3) scores = scale * Q^T K : [4096x4096], K-dim = 512
    dim3 gs(NS / TBN, NS / TBM, BATCH);
    float scale = 1.0f / sqrtf((float)CH);
    gemm_tn<<<gs, 256>>>(qP, kP, aP, scale, NS, NS, CH, SB, SB, SA);

    // 4) row-wise softmax over j
    softmax_kernel<<<BATCH * NS, 256>>>(aP);

    // 5) o[c,i] = sum_j attn[i,j] * v[c,j]  (NT)
    dim3 go(NS / TBN, CH / TBM, BATCH);
    gemm_nt<<<go, 256>>>(vP, aP, oP, CH, NS, NS, SB, SA, SB);

    // 6) out = x + Wo @ o + bo
    gemm_nn<<<gq, 256>>>(wo, oP, out, bo, x, CH, NS, CH, SB, SB, SB);
}

// round 5
// speedup vs baseline: 2.4902x; 2.4902x over previous
#include <cuda_runtime.h>
#include <cstdint>
#include <math.h>

#define BATCH 2
#define CH    512
#define NS    4096
#define NGRP  32

#define BM 128
#define BN 128
#define BK 16
#define BKP 17   // padded row stride (floats) — conflict-free fragment loads

// ---------------- scratch (static device memory) ---------------------------
__device__ float g_hT[(size_t)BATCH * NS * CH];
__device__ float g_qT[(size_t)BATCH * NS * CH];
__device__ float g_kT[(size_t)BATCH * NS * CH];
__device__ float g_v [(size_t)BATCH * CH * NS];
__device__ float g_oT[(size_t)BATCH * NS * CH];
__device__ float g_attn[(size_t)BATCH * NS * NS];

__device__ __forceinline__ uint32_t f2tf32(float x) {
    uint32_t y; asm("cvt.rna.tf32.f32 %0, %1;" : "=r"(y) : "f"(x)); return y;
}

__device__ __forceinline__ void mma_tf32(float c[4], uint32_t a0, uint32_t a1,
                                         uint32_t a2, uint32_t a3,
                                         uint32_t b0, uint32_t b1) {
    asm volatile(
        "mma.sync.aligned.m16n8k8.row.col.f32.tf32.tf32.f32 "
        "{%0,%1,%2,%3}, {%4,%5,%6,%7}, {%8,%9}, {%0,%1,%2,%3};"
        : "+f"(c[0]), "+f"(c[1]), "+f"(c[2]), "+f"(c[3])
        : "r"(a0), "r"(a1), "r"(a2), "r"(a3), "r"(b0), "r"(b1));
}

// ---------------- tensor-core GEMM: C[M,N] = A[M,K] * B[N,K]^T --------------
// biasMode: 0 none, 1 row (bias[m]), 2 col (bias[n]). val=(acc+bias)*scale+res
__global__ void __launch_bounds__(256) tc_gemm(
    const float* __restrict__ A, const float* __restrict__ B,
    float* __restrict__ C, const float* __restrict__ bias, int biasMode,
    float scale, const float* __restrict__ res,
    int K, int lda, int ldb, int ldc,
    long long sA, long long sB, long long sC, long long sR)
{
    __shared__ uint32_t As[2][BM * BKP];
    __shared__ uint32_t Bs[2][BN * BKP];

    const int tid  = threadIdx.x;
    const int wid  = tid >> 5, lane = tid & 31;
    const int qm   = lane >> 2;       // 0..7
    const int qk   = lane & 3;        // 0..3
    const int wm0  = (wid >> 2) * 64; // warp m origin within tile (2 rows of warps)
    const int wn0  = (wid & 3) * 32;  // warp n origin (4 cols of warps)

    const float* Ap = A + (long long)blockIdx.z * sA;
    const float* Bp = B + (long long)blockIdx.z * sB;
    float*       Cp = C + (long long)blockIdx.z * sC;
    const float* Rp = res ? res + (long long)blockIdx.z * sR : nullptr;
    const int m0 = blockIdx.y * BM;
    const int n0 = blockIdx.x * BN;

    // staging indices: 512 float4 per tile, 2 per thread
    const int f0 = tid, f1 = tid + 256;      // float4 index
    const int ar0 = f0 >> 2, ac0 = (f0 & 3) * 4;
    const int ar1 = f1 >> 2, ac1 = (f1 & 3) * 4;

    float acc[4][4][4];
#pragma unroll
    for (int i = 0; i < 4; i++)
#pragma unroll
        for (int j = 0; j < 4; j++)
#pragma unroll
            for (int r = 0; r < 4; r++) acc[i][j][r] = 0.f;

    const int nch = K / BK;
    float4 stA0, stA1, stB0, stB1;

    // prologue: load chunk 0
    stA0 = *(const float4*)(Ap + (size_t)(m0 + ar0) * lda + ac0);
    stA1 = *(const float4*)(Ap + (size_t)(m0 + ar1) * lda + ac1);
    stB0 = *(const float4*)(Bp + (size_t)(n0 + ar0) * ldb + ac0);
    stB1 = *(const float4*)(Bp + (size_t)(n0 + ar1) * ldb + ac1);

    for (int ch = 0; ch < nch; ch++) {
        const int buf = ch & 1;
        // store staged chunk into smem (with tf32 rounding)
        {
            uint32_t* a0p = &As[buf][ar0 * BKP + ac0];
            a0p[0] = f2tf32(stA0.x); a0p[1] = f2tf32(stA0.y);
            a0p[2] = f2tf32(stA0.z); a0p[3] = f2tf32(stA0.w);
            uint32_t* a1p = &As[buf][ar1 * BKP + ac1];
            a1p[0] = f2tf32(stA1.x); a1p[1] = f2tf32(stA1.y);
            a1p[2] = f2tf32(stA1.z); a1p[3] = f2tf32(stA1.w);
            uint32_t* b0p = &Bs[buf][ar0 * BKP + ac0];
            b0p[0] = f2tf32(stB0.x); b0p[1] = f2tf32(stB0.y);
            b0p[2] = f2tf32(stB0.z); b0p[3] = f2tf32(stB0.w);
            uint32_t* b1p = &Bs[buf][ar1 * BKP + ac1];
            b1p[0] = f2tf32(stB1.x); b1p[1] = f2tf32(stB1.y);
            b1p[2] = f2tf32(stB1.z); b1p[3] = f2tf32(stB1.w);
        }
        __syncthreads();
        // issue global loads for next chunk (latency hidden by compute)
        if (ch + 1 < nch) {
            const float* an = Ap + (size_t)m0 * lda + (ch + 1) * BK;
            const float* bn = Bp + (size_t)n0 * ldb + (ch + 1) * BK;
            stA0 = *(const float4*)(an + (size_t)ar0 * lda + ac0);
            stA1 = *(const float4*)(an + (size_t)ar1 * lda + ac1);
            stB0 = *(const float4*)(bn + (size_t)ar0 * ldb + ac0);
            stB1 = *(const float4*)(bn + (size_t)ar1 * ldb + ac1);
        }
        // compute: 2 k-steps of 8
#pragma unroll
        for (int ks = 0; ks < 2; ks++) {
            const int k0 = ks * 8;
            uint32_t afr[4][4], bfr[4][2];
#pragma unroll
            for (int mt = 0; mt < 4; mt++) {
                const uint32_t* base = &As[buf][(wm0 + mt * 16 + qm) * BKP + k0 + qk];
                afr[mt][0] = base[0];
                afr[mt][1] = base[8 * BKP];
                afr[mt][2] = base[4];
                afr[mt][3] = base[8 * BKP + 4];
            }
#pragma unroll
            for (int nt = 0; nt < 4; nt++) {
                const uint32_t* base = &Bs[buf][(wn0 + nt * 8 + qm) * BKP + k0 + qk];
                bfr[nt][0] = base[0];
                bfr[nt][1] = base[4];
            }
#pragma unroll
            for (int mt = 0; mt < 4; mt++)
#pragma unroll
                for (int nt = 0; nt < 4; nt++)
                    mma_tf32(acc[mt][nt], afr[mt][0], afr[mt][1], afr[mt][2],
                             afr[mt][3], bfr[nt][0], bfr[nt][1]);
        }
        __syncthreads();
    }

    // epilogue: c0:(r,2c) c1:(r,2c+1) c2:(r+8,2c) c3:(r+8,2c+1)
#pragma unroll
    for (int mt = 0; mt < 4; mt++) {
        const int mr = m0 + wm0 + mt * 16 + qm;
#pragma unroll
        for (int nt = 0; nt < 4; nt++) {
            const int nc = n0 + wn0 + nt * 8 + qk * 2;
            float v0 = acc[mt][nt][0], v1 = acc[mt][nt][1];
            float v2 = acc[mt][nt][2], v3 = acc[mt][nt][3];
            if (biasMode == 1) {
                float b0 = bias[mr], b1 = bias[mr + 8];
                v0 += b0; v1 += b0; v2 += b1; v3 += b1;
            } else if (biasMode == 2) {
                float b0 = bias[nc], b1 = bias[nc + 1];
                v0 += b0; v1 += b1; v2 += b0; v3 += b1;
            }
            v0 *= scale; v1 *= scale; v2 *= scale; v3 *= scale;
            if (Rp) {
                float2 r0 = *(const float2*)(Rp + (size_t)mr * ldc + nc);
                float2 r1 = *(const float2*)(Rp + (size_t)(mr + 8) * ldc + nc);
                v0 += r0.x; v1 += r0.y; v2 += r1.x; v3 += r1.y;
            }
            *(float2*)(Cp + (size_t)mr * ldc + nc)       = make_float2(v0, v1);
            *(float2*)(Cp + (size_t)(mr + 8) * ldc + nc) = make_float2(v2, v3);
        }
    }
}

// ---------------- GroupNorm -> transposed hT[n, c] --------------------------
__global__ void __launch_bounds__(256) gn_kernel(
    const float* __restrict__ x, const float* __restrict__ gamma,
    const float* __restrict__ beta, float* __restrict__ hT)
{
    int blk = blockIdx.x;
    int b = blk >> 5, grp = blk & 31;
    size_t base = ((size_t)(b * CH + grp * 16)) * NS;
    const float4* x4 = (const float4*)(x + base);
    const int n4 = 16 * NS / 4;

    float s = 0.f, ss = 0.f;
    for (int i = threadIdx.x; i < n4; i += 256) {
        float4 v = x4[i];
        s  += v.x + v.y + v.z + v.w;
        ss += v.x * v.x + v.y * v.y + v.z * v.z + v.w * v.w;
    }
    __shared__ float rs[256], rss[256];
    rs[threadIdx.x] = s; rss[threadIdx.x] = ss;
    __syncthreads();
    for (int st = 128; st > 0; st >>= 1) {
        if (threadIdx.x < st) {
            rs[threadIdx.x]  += rs[threadIdx.x + st];
            rss[threadIdx.x] += rss[threadIdx.x + st];
        }
        __syncthreads();
    }
    const float inv_n = 1.f / (16.f * NS);
    float mean = rs[0] * inv_n;
    float var  = rss[0] * inv_n - mean * mean;
    float inv  = rsqrtf(var + 1e-6f);

    // pass 2: transpose 16c x 64n tiles via smem
    __shared__ float tt[64][17];
    const int cc = threadIdx.x & 15;     // channel
    const int nn = threadIdx.x >> 4;     // 0..15
    float ga = gamma[grp * 16 + cc] * inv;
    float be = beta[grp * 16 + cc] - mean * ga;
    float* outp = hT + ((size_t)b * NS) * CH + grp * 16;
    const float* inp = x + base;

    for (int t0 = 0; t0 < NS; t0 += 64) {
#pragma unroll
        for (int u = 0; u < 4; u++) {
            float v = inp[(size_t)cc * NS + t0 + u * 16 + nn];
            tt[u * 16 + nn][cc] = v * ga + be;
        }
        __syncthreads();
#pragma unroll
        for (int u = 0; u < 4; u++)
            outp[(size_t)(t0 + u * 16 + nn) * CH + cc] = tt[u * 16 + nn][cc];
        __syncthreads();
    }
}

// ---------------- Softmax (rows of 4096) ------------------------------------
__global__ void __launch_bounds__(256) softmax_kernel(float* __restrict__ attn)
{
    float4* p = (float4*)(attn + (size_t)blockIdx.x * NS);
    __shared__ float red[256];
    int t = threadIdx.x;

    float m = -1e30f;
    for (int i = t; i < NS / 4; i += 256) {
        float4 v = p[i];
        m = fmaxf(m, fmaxf(fmaxf(v.x, v.y), fmaxf(v.z, v.w)));
    }
    red[t] = m; __syncthreads();
    for (int st = 128; st > 0; st >>= 1) {
        if (t < st) red[t] = fmaxf(red[t], red[t + st]);
        __syncthreads();
    }
    m = red[0];
    __syncthreads();

    float s = 0.f;
    for (int i = t; i < NS / 4; i += 256) {
        float4 v = p[i];
        v.x = __expf(v.x - m); v.y = __expf(v.y - m);
        v.z = __expf(v.z - m); v.w = __expf(v.w - m);
        p[i] = v;
        s += v.x + v.y + v.z + v.w;
    }
    red[t] = s; __syncthreads();
    for (int st = 128; st > 0; st >>= 1) {
        if (t < st) red[t] += red[t + st];
        __syncthreads();
    }
    float inv = 1.f / red[0];
    for (int i = t; i < NS / 4; i += 256) {
        float4 v = p[i];
        v.x *= inv; v.y *= inv; v.z *= inv; v.w *= inv;
        p[i] = v;
    }
}

// ---------------- launch ----------------------------------------------------
extern "C" void kernel_launch(void* const* d_in, const int* in_sizes, int n_in,
                              void* d_out, int out_size)
{
    const float* x     = (const float*)d_in[0];
    const float* gamma = (const float*)d_in[1];
    const float* beta  = (const float*)d_in[2];
    const float* wq = (const float*)d_in[3];
    const float* bq = (const float*)d_in[4];
    const float* wk = (const float*)d_in[5];
    const float* bk = (const float*)d_in[6];
    const float* wv = (const float*)d_in[7];
    const float* bv = (const float*)d_in[8];
    const float* wo = (const float*)d_in[9];
    const float* bo = (const float*)d_in[10];
    float* out = (float*)d_out;

    float *hT, *qT, *kT, *vP, *oT, *aP;
    cudaGetSymbolAddress((void**)&hT, g_hT);
    cudaGetSymbolAddress((void**)&qT, g_qT);
    cudaGetSymbolAddress((void**)&kT, g_kT);
    cudaGetSymbolAddress((void**)&vP, g_v);
    cudaGetSymbolAddress((void**)&oT, g_oT);
    cudaGetSymbolAddress((void**)&aP, g_attn);

    const long long SNC = (long long)NS * CH;
    const long long SAA = (long long)NS * NS;
    const float qscale = 1.0f / sqrtf((float)CH);

    // 1) GroupNorm -> hT[b][n][c]
    gn_kernel<<<BATCH * NGRP, 256>>>(x, gamma, beta, hT);

    // 2) qT[n,co] = hT·wq^T (col bias, qscale folded); kT likewise
    dim3 gP(CH / BN, NS / BM, BATCH);
    tc_gemm<<<gP, 256>>>(hT, wq, qT, bq, 2, qscale, nullptr,
                         CH, CH, CH, CH, SNC, 0, SNC, 0);
    tc_gemm<<<gP, 256>>>(hT, wk, kT, bk, 2, 1.f, nullptr,
                         CH, CH, CH, CH, SNC, 0, SNC, 0);
    //    v[co,n] = wv·hT^T (row bias)
    dim3 gV(NS / BN, CH / BM, BATCH);
    tc_gemm<<<gV, 256>>>(wv, hT, vP, bv, 1, 1.f, nullptr,
                         CH, CH, CH, NS, 0, SNC, SNC, 0);

    // 3) scores[i,j] = qT·kT^T
    dim3 gS(NS / BN, NS / BM, BATCH);
    tc_gemm<<<gS, 256>>>(qT, kT, aP, nullptr, 0, 1.f, nullptr,
                         CH, CH, CH, NS, SNC, SNC, SAA, 0);

    // 4) softmax rows
    softmax_kernel<<<BATCH * NS, 256>>>(aP);

    // 5) oT[i,c] = attn·v^T (K = NS)
    dim3 gO(CH / BN, NS / BM, BATCH);
    tc_gemm<<<gO, 256>>>(aP, vP, oT, nullptr, 0, 1.f, nullptr,
                         NS, NS, NS, CH, SAA, SNC, SNC, 0);

    // 6) out[co,n] = wo·oT^T + bo + x
    dim3 gF(NS / BN, CH / BM, BATCH);
    tc_gemm<<<gF, 256>>>(wo, oT, out, bo, 1, 1.f, x,
                         CH, CH, CH, NS, 0, SNC, SNC, SNC);
}